// round 11
// baseline (speedup 1.0000x reference)
#include <cuda_runtime.h>
#include <math.h>

#define NSEQ   24
#define LSEQ   8192
#define NCHUNK 128
#define CIN    16
#define DIN    64
#define NH     16
#define HD     4
#define DSTATE 64
#define CONVDIM 192
#define DPROJ  272

// ---------------- scratch ----------------
__device__ float  g_z     [NSEQ*LSEQ*DIN];
__device__ float  g_xBCp  [NSEQ*LSEQ*CONVDIM];
__device__ float  g_xBC   [NSEQ*LSEQ*CONVDIM];   // [0:64]=xh [64:128]=B [128:192]=C
__device__ float2 g_dtA   [NSEQ*LSEQ*NH];        // (dt, dA)
__device__ float  g_ylocal[NSEQ*LSEQ*DIN];
__device__ float  g_cumdec[NSEQ*LSEQ*NH];
__device__ float  g_T     [NSEQ*NCHUNK*4096];
__device__ float  g_Sprev [NSEQ*NCHUNK*4096];    // segment-LOCAL entering states
__device__ float  g_segend[NSEQ*4*4096];         // segment-end local states
__device__ float  g_entry [NSEQ*4*4096];         // global state entering each segment
__device__ float  g_prefix[NSEQ*NCHUNK*NH];      // prod of chunk decays from seg start to ck-1
__device__ float  g_v     [NSEQ*LSEQ*CIN];
__device__ float  g_bnpart[3*64*32];
__device__ float  g_coefw [3*CIN];
__device__ float  g_coefc [3];

__device__ __forceinline__ float silu_f(float x) { return x / (1.f + expf(-x)); }

typedef unsigned long long u64t;
__device__ __forceinline__ u64t pack2(float a, float b) {
    u64t r; asm("mov.b64 %0, {%1,%2};" : "=l"(r) : "f"(a), "f"(b)); return r;
}
__device__ __forceinline__ float2 unpack2(u64t v) {
    float2 f; asm("mov.b64 {%0,%1}, %2;" : "=f"(f.x), "=f"(f.y) : "l"(v)); return f;
}
#define FMA2(d,a,b,c) asm("fma.rn.f32x2 %0,%1,%2,%3;" : "=l"(d) : "l"(a), "l"(b), "l"(c))
#define MUL2(d,a,b)   asm("mul.rn.f32x2 %0,%1,%2;"    : "=l"(d) : "l"(a), "l"(b))

// ---------------- K1: input gather + in-projection (272x16) ----------------
__global__ void k1_proj(const float* __restrict__ x, const float* __restrict__ Win,
                        const float* __restrict__ dt_bias, const float* __restrict__ A_log) {
    int blk  = blockIdx.x;
    int seq  = blk >> 8;
    int tile = blk & 255;
    int dir  = seq / 8, b = seq % 8;
    int l0   = tile * 32;
    int tid  = threadIdx.x;

    __shared__ __align__(16) float us[32 * 16];

    for (int i = tid; i < 512; i += 288) {
        int c = i >> 5, tok = i & 31;
        int l = l0 + tok;
        int xl;
        if (dir == 0) {
            xl = l;
        } else if (dir == 1) {
            int dd = l & 31, ww = (l >> 5) & 15, hh = l >> 9;
            xl = dd * 256 + hh * 16 + ww;
        } else {
            int hh = l & 15, dd = (l >> 4) & 31, ww = l >> 9;
            xl = dd * 256 + hh * 16 + ww;
        }
        us[tok * 16 + c] = x[(b * 16 + c) * 8192 + xl];
    }
    __syncthreads();

    int f = tid;
    if (f >= 272) return;

    float w[16];
    {
        const float4* W4 = reinterpret_cast<const float4*>(Win + (dir * 272 + f) * 16);
        #pragma unroll
        for (int q = 0; q < 4; q++) {
            float4 t = W4[q];
            w[q*4+0] = t.x; w[q*4+1] = t.y; w[q*4+2] = t.z; w[q*4+3] = t.w;
        }
    }
    float dtb = 0.f, Aneg = 0.f;
    if (f >= 256) {
        int h = f - 256;
        dtb  = dt_bias[dir * 16 + h];
        Aneg = -expf(A_log[dir * 16 + h]);
    }

    for (int tok = 0; tok < 32; tok++) {
        const float4* u4 = reinterpret_cast<const float4*>(us + tok * 16);
        float acc = 0.f;
        #pragma unroll
        for (int q = 0; q < 4; q++) {
            float4 t = u4[q];
            acc += t.x * w[q*4+0] + t.y * w[q*4+1] + t.z * w[q*4+2] + t.w * w[q*4+3];
        }
        int bl = seq * LSEQ + (l0 + tok);
        if (f < 64) {
            g_z[bl * 64 + f] = acc;
        } else if (f < 256) {
            g_xBCp[bl * 192 + (f - 64)] = acc;
        } else {
            int h = f - 256;
            float v  = acc + dtb;
            float dt = fmaxf(v, 0.f) + log1pf(expf(-fabsf(v)));
            g_dtA[bl * 16 + h] = make_float2(dt, expf(dt * Aneg));
        }
    }
}

// ---------------- K2: causal depthwise conv (k=4) + SiLU, smem-tiled ----------------
__global__ void k2_conv(const float* __restrict__ conv_w, const float* __restrict__ conv_b) {
    int blk  = blockIdx.x;
    int seq  = blk >> 8;
    int tile = blk & 255;
    int dir  = seq / 8;
    int l0   = tile * 32;
    int tid  = threadIdx.x;

    __shared__ float s[35 * 192];

    for (int i = tid; i < 35 * 192; i += 256) {
        int r = i / 192, ch = i - r * 192;
        int l = l0 - 3 + r;
        s[i] = (l >= 0) ? g_xBCp[(seq * LSEQ + l) * 192 + ch] : 0.f;
    }
    __syncthreads();

    for (int i = tid; i < 32 * 192; i += 256) {
        int tok = i / 192, ch = i - tok * 192;
        float4 w = *reinterpret_cast<const float4*>(conv_w + (dir * 192 + ch) * 4);
        float acc = conv_b[dir * 192 + ch]
                  + s[(tok    ) * 192 + ch] * w.x
                  + s[(tok + 1) * 192 + ch] * w.y
                  + s[(tok + 2) * 192 + ch] * w.z
                  + s[(tok + 3) * 192 + ch] * w.w;
        g_xBC[(seq * LSEQ + l0 + tok) * 192 + ch] = silu_f(acc);
    }
}

// ---------------- K3: chunk-local scan, 4 lanes/head, 16 states/lane ----------------
__global__ void __launch_bounds__(128) k3_scan() {
    int gw   = blockIdx.x * 4 + (threadIdx.x >> 5);   // global warp id
    int lane = threadIdx.x & 31;
    int half  = gw & 1;
    int chunk = (gw >> 1) & 127;
    int seq   = gw >> 8;
    if (seq >= NSEQ) return;

    int li = lane & 3;                 // quad index: 16 states each
    int h  = half * 8 + (lane >> 2);   // head
    int n0 = li * 16;

    u64t S2[4][8];
    #pragma unroll
    for (int p = 0; p < 4; p++)
        #pragma unroll
        for (int j = 0; j < 8; j++) S2[p][j] = 0ull;
    float cum = 1.f;

    int lbase = seq * LSEQ + chunk * 64;
    #pragma unroll 1
    for (int t = 0; t < 64; t++) {
        int bl = lbase + t;
        float2 dta = g_dtA[bl * 16 + h];       // (dt, dA)
        cum *= dta.y;
        float4 xh4 = *reinterpret_cast<const float4*>(g_xBC + bl * 192 + h * 4);
        u64t B2[8], C2[8];
        {
            const ulonglong2* bp = reinterpret_cast<const ulonglong2*>(g_xBC + bl * 192 + 64 + n0);
            const ulonglong2* cp = reinterpret_cast<const ulonglong2*>(g_xBC + bl * 192 + 128 + n0);
            #pragma unroll
            for (int q = 0; q < 4; q++) {
                ulonglong2 bv = bp[q];
                ulonglong2 cv = cp[q];
                B2[q*2+0] = bv.x; B2[q*2+1] = bv.y;
                C2[q*2+0] = cv.x; C2[q*2+1] = cv.y;
            }
        }

        u64t dA2 = pack2(dta.y, dta.y);
        float xh[4] = { xh4.x, xh4.y, xh4.z, xh4.w };
        u64t dtx2[4];
        #pragma unroll
        for (int p = 0; p < 4; p++) {
            float d_ = dta.x * xh[p];
            dtx2[p] = pack2(d_, d_);
        }

        float acc[4];
        #pragma unroll
        for (int p = 0; p < 4; p++) {
            u64t a, tp;
            MUL2(tp, dtx2[p], B2[0]);
            FMA2(S2[p][0], S2[p][0], dA2, tp);
            MUL2(a, S2[p][0], C2[0]);
            #pragma unroll
            for (int j = 1; j < 8; j++) {
                MUL2(tp, dtx2[p], B2[j]);
                FMA2(S2[p][j], S2[p][j], dA2, tp);
                FMA2(a, S2[p][j], C2[j], a);
            }
            float2 f = unpack2(a);
            acc[p] = f.x + f.y;
        }
        // reduce over the 4 lanes of the quad (offsets 2, 1)
        #pragma unroll
        for (int off = 2; off >= 1; off >>= 1) {
            #pragma unroll
            for (int p = 0; p < 4; p++)
                acc[p] += __shfl_xor_sync(0xffffffffu, acc[p], off);
        }
        if (li == 0) {
            *reinterpret_cast<float4*>(g_ylocal + bl * 64 + h * 4) =
                make_float4(acc[0], acc[1], acc[2], acc[3]);
            g_cumdec[bl * 16 + h] = cum;
        }
    }
    // store end-of-chunk local state T  [h][p][n]
    int tb = (seq * 128 + chunk) * 4096 + h * 256;
    #pragma unroll
    for (int p = 0; p < 4; p++) {
        #pragma unroll
        for (int q = 0; q < 4; q++) {
            ulonglong2 v; v.x = S2[p][q*2]; v.y = S2[p][q*2+1];
            *reinterpret_cast<ulonglong2*>(g_T + tb + p * 64 + n0 + q * 4) = v;
        }
    }
}

// ---------------- K4a: segment-local state scans (fully parallel) ----------------
// grid = NSEQ * NH * 4 segments; block 256 (one per state element of head h)
__global__ void k4a_segscan() {
    int b    = blockIdx.x;
    int seq  = b >> 6;
    int rem  = b & 63;
    int h    = rem >> 2;
    int seg  = rem & 3;
    int elem = h * 256 + threadIdx.x;

    __shared__ float dec[32];
    if (threadIdx.x < 32)
        dec[threadIdx.x] = g_cumdec[(seq * LSEQ + (seg * 32 + threadIdx.x) * 64 + 63) * 16 + h];
    __syncthreads();

    int ck0 = seg * 32;
    float S  = 0.f;
    float Tn = g_T[(seq * 128 + ck0) * 4096 + elem];
    #pragma unroll 4
    for (int j = 0; j < 32; j++) {
        int base = (seq * 128 + ck0 + j) * 4096 + elem;
        g_Sprev[base] = S;                     // segment-LOCAL entering state
        float Tc = Tn;
        if (j < 31) Tn = g_T[base + 4096];
        S = fmaf(S, dec[j], Tc);
    }
    g_segend[(seq * 4 + seg) * 4096 + elem] = S;
}

// ---------------- K4b: combine segments + decay prefixes ----------------
// grid = NSEQ, block 1024
__global__ void k4b_combine() {
    int seq = blockIdx.x;
    int tid = threadIdx.x;
    __shared__ float DECs[4][16];

    if (tid < 64) {
        int s = tid >> 4, h = tid & 15;
        float p = 1.f;
        for (int j = 0; j < 32; j++) {
            int ck = s * 32 + j;
            g_prefix[(seq * 128 + ck) * 16 + h] = p;
            p *= g_cumdec[(seq * LSEQ + ck * 64 + 63) * 16 + h];
        }
        DECs[s][h] = p;
    }
    __syncthreads();

    int elem = tid * 4;
    int h    = elem >> 8;
    float4 e = make_float4(0.f, 0.f, 0.f, 0.f);
    #pragma unroll
    for (int s = 0; s < 4; s++) {
        *reinterpret_cast<float4*>(g_entry + (seq * 4 + s) * 4096 + elem) = e;
        float4 E = *reinterpret_cast<const float4*>(g_segend + (seq * 4 + s) * 4096 + elem);
        float d = DECs[s][h];
        e.x = e.x * d + E.x;
        e.y = e.y * d + E.y;
        e.z = e.z * d + E.z;
        e.w = e.w * d + E.w;
    }
}

// ---------------- K5: inter-chunk correction + gating + RMSNorm + out-proj + ReLU ----------------
__global__ void __launch_bounds__(1024, 2) k5_fused(const float* __restrict__ Dp,
                                                    const float* __restrict__ Wout,
                                                    const float* __restrict__ norm_w) {
    int bid   = blockIdx.x;
    int seq   = bid >> 7;
    int chunk = bid & 127;
    int dir   = seq / 8;
    int tid   = threadIdx.x;
    int h     = tid >> 6;
    int t     = tid & 63;

    __shared__ __align__(16) float Sp[4096];
    __shared__ float CsY[64 * 65];
    __shared__ float ssq[1024];
    __shared__ __align__(16) float Ws[1024];
    __shared__ float nww[64];

    {
        int elem = tid * 4;          // elem>>8 == h for this thread
        float pref = g_prefix[(seq * 128 + chunk) * 16 + h];
        float4 sv = *reinterpret_cast<const float4*>(g_Sprev + (seq * 128 + chunk) * 4096 + elem);
        float4 ev = *reinterpret_cast<const float4*>(g_entry + (seq * 4 + (chunk >> 5)) * 4096 + elem);
        Sp[elem + 0] = fmaf(pref, ev.x, sv.x);
        Sp[elem + 1] = fmaf(pref, ev.y, sv.y);
        Sp[elem + 2] = fmaf(pref, ev.z, sv.z);
        Sp[elem + 3] = fmaf(pref, ev.w, sv.w);
    }
    {
        int flat = tid * 4;
        int tr = flat >> 6, nc = flat & 63;
        float4 v = *reinterpret_cast<const float4*>(
            g_xBC + (seq * LSEQ + chunk * 64 + tr) * 192 + 128 + nc);
        CsY[tr * 65 + nc + 0] = v.x;
        CsY[tr * 65 + nc + 1] = v.y;
        CsY[tr * 65 + nc + 2] = v.z;
        CsY[tr * 65 + nc + 3] = v.w;
    }
    if (tid < 1024) Ws[tid] = Wout[dir * 1024 + tid];
    if (tid < 64)   nww[tid] = norm_w[dir * 64 + tid];
    __syncthreads();

    const float* Sh = Sp + h * 256;
    const float* Ct = CsY + t * 65;
    float a0 = 0.f, a1 = 0.f, a2 = 0.f, a3 = 0.f;
    #pragma unroll 4
    for (int n = 0; n < 64; n += 4) {
        float c0 = Ct[n], c1 = Ct[n + 1], c2 = Ct[n + 2], c3 = Ct[n + 3];
        float4 s;
        s = *reinterpret_cast<const float4*>(Sh + n);        a0 += c0*s.x + c1*s.y + c2*s.z + c3*s.w;
        s = *reinterpret_cast<const float4*>(Sh + 64 + n);   a1 += c0*s.x + c1*s.y + c2*s.z + c3*s.w;
        s = *reinterpret_cast<const float4*>(Sh + 128 + n);  a2 += c0*s.x + c1*s.y + c2*s.z + c3*s.w;
        s = *reinterpret_cast<const float4*>(Sh + 192 + n);  a3 += c0*s.x + c1*s.y + c2*s.z + c3*s.w;
    }

    int bl = seq * LSEQ + chunk * 64 + t;
    float cd   = g_cumdec[bl * 16 + h];
    float4 yl  = *reinterpret_cast<const float4*>(g_ylocal + bl * 64 + h * 4);
    float4 xh  = *reinterpret_cast<const float4*>(g_xBC + bl * 192 + h * 4);
    float4 z4  = *reinterpret_cast<const float4*>(g_z + bl * 64 + h * 4);
    float dp   = Dp[dir * 16 + h];

    float o0 = (yl.x + cd * a0 + dp * xh.x) * silu_f(z4.x);
    float o1 = (yl.y + cd * a1 + dp * xh.y) * silu_f(z4.y);
    float o2 = (yl.z + cd * a2 + dp * xh.z) * silu_f(z4.z);
    float o3 = (yl.w + cd * a3 + dp * xh.w) * silu_f(z4.w);

    ssq[tid] = o0*o0 + o1*o1 + o2*o2 + o3*o3;
    __syncthreads();

    float ss = 0.f;
    #pragma unroll
    for (int hh = 0; hh < 16; hh++) ss += ssq[hh * 64 + t];
    float scale = rsqrtf(ss * (1.f / 64.f) + 1e-5f);

    CsY[(h * 4 + 0) * 65 + t] = o0 * scale * nww[h * 4 + 0];
    CsY[(h * 4 + 1) * 65 + t] = o1 * scale * nww[h * 4 + 1];
    CsY[(h * 4 + 2) * 65 + t] = o2 * scale * nww[h * 4 + 2];
    CsY[(h * 4 + 3) * 65 + t] = o3 * scale * nww[h * 4 + 3];
    __syncthreads();

    float acc = 0.f;
    const float4* w4 = reinterpret_cast<const float4*>(Ws + h * 64);
    #pragma unroll 4
    for (int d = 0; d < 64; d += 4) {
        float4 w = w4[d >> 2];
        acc += CsY[(d    ) * 65 + t] * w.x
             + CsY[(d + 1) * 65 + t] * w.y
             + CsY[(d + 2) * 65 + t] * w.z
             + CsY[(d + 3) * 65 + t] * w.w;
    }
    g_v[bl * 16 + h] = fmaxf(acc, 0.f);
}

// ---------------- K6a/K6b: deterministic BN statistics + folded coefficients ----------------
__global__ void k6a_bnstats() {
    int dir = blockIdx.x >> 6;
    int blk = blockIdx.x & 63;
    int tid = threadIdx.x;

    float sum[16], sq[16];
    #pragma unroll
    for (int c = 0; c < 16; c++) { sum[c] = 0.f; sq[c] = 0.f; }

    int rowbase = dir * 65536 + blk * 1024;
    for (int r = tid; r < 1024; r += 256) {
        const float4* v4 = reinterpret_cast<const float4*>(g_v + (rowbase + r) * 16);
        #pragma unroll
        for (int q = 0; q < 4; q++) {
            float4 v = v4[q];
            sum[q*4+0] += v.x; sq[q*4+0] += v.x*v.x;
            sum[q*4+1] += v.y; sq[q*4+1] += v.y*v.y;
            sum[q*4+2] += v.z; sq[q*4+2] += v.z*v.z;
            sum[q*4+3] += v.w; sq[q*4+3] += v.w*v.w;
        }
    }
    __shared__ float red[256 * 32];
    #pragma unroll
    for (int c = 0; c < 16; c++) {
        red[tid * 32 + c]      = sum[c];
        red[tid * 32 + 16 + c] = sq[c];
    }
    __syncthreads();
    if (tid < 32) {
        float tot = 0.f;
        for (int r = 0; r < 256; r++) tot += red[r * 32 + tid];
        g_bnpart[(dir * 64 + blk) * 32 + tid] = tot;
    }
}

__global__ void k6b_coef(const float* __restrict__ gamma, const float* __restrict__ beta,
                         const float* __restrict__ lin_w, const float* __restrict__ lin_b) {
    int tid = threadIdx.x;
    __shared__ float cpart[3][16];
    if (tid < 48) {
        int dir = tid / 16, c = tid % 16;
        float s = 0.f, q = 0.f;
        for (int blk = 0; blk < 64; blk++) {
            s += g_bnpart[(dir * 64 + blk) * 32 + c];
            q += g_bnpart[(dir * 64 + blk) * 32 + 16 + c];
        }
        float mu  = s * (1.f / 65536.f);
        float var = q * (1.f / 65536.f) - mu * mu;
        float inv = rsqrtf(var + 1e-5f);
        float g  = gamma[dir * 16 + c];
        float bt = beta[dir * 16 + c];
        float lw = lin_w[dir * 16 + c];
        g_coefw[dir * 16 + c] = inv * g * lw;
        cpart[dir][c] = (bt - mu * inv * g) * lw;
    }
    __syncthreads();
    if (tid < 3) {
        float s = lin_b[tid];
        for (int c = 0; c < 16; c++) s += cpart[tid][c];
        g_coefc[tid] = s;
    }
}

// ---------------- K7: linear + adaptive max pool ----------------
__global__ void k7_pool(float* __restrict__ out) {
    int bid  = blockIdx.x;
    int seq  = bid >> 8;
    int pool = bid & 255;
    int dir  = seq / 8, b = seq % 8;
    int lane = threadIdx.x;

    float4 cw0 = *reinterpret_cast<const float4*>(g_coefw + dir * 16);
    float4 cw1 = *reinterpret_cast<const float4*>(g_coefw + dir * 16 + 4);
    float4 cw2 = *reinterpret_cast<const float4*>(g_coefw + dir * 16 + 8);
    float4 cw3 = *reinterpret_cast<const float4*>(g_coefw + dir * 16 + 12);

    int bl = seq * LSEQ + pool * 32 + lane;
    const float4* v4 = reinterpret_cast<const float4*>(g_v + bl * 16);
    float s = g_coefc[dir];
    float4 v;
    v = v4[0]; s += v.x*cw0.x + v.y*cw0.y + v.z*cw0.z + v.w*cw0.w;
    v = v4[1]; s += v.x*cw1.x + v.y*cw1.y + v.z*cw1.z + v.w*cw1.w;
    v = v4[2]; s += v.x*cw2.x + v.y*cw2.y + v.z*cw2.z + v.w*cw2.w;
    v = v4[3]; s += v.x*cw3.x + v.y*cw3.y + v.z*cw3.z + v.w*cw3.w;

    #pragma unroll
    for (int off = 16; off >= 1; off >>= 1)
        s = fmaxf(s, __shfl_xor_sync(0xffffffffu, s, off));
    if (lane == 0) out[b * 768 + dir * 256 + pool] = s;
}

// ---------------- launch ----------------
extern "C" void kernel_launch(void* const* d_in, const int* in_sizes, int n_in,
                              void* d_out, int out_size) {
    const float* x       = (const float*)d_in[0];
    const float* Win     = (const float*)d_in[1];
    const float* conv_w  = (const float*)d_in[2];
    const float* conv_b  = (const float*)d_in[3];
    const float* dt_bias = (const float*)d_in[4];
    const float* A_log   = (const float*)d_in[5];
    const float* Dp      = (const float*)d_in[6];
    const float* norm_w  = (const float*)d_in[7];
    const float* Wout    = (const float*)d_in[8];
    const float* gamma   = (const float*)d_in[9];
    const float* beta    = (const float*)d_in[10];
    const float* lin_w   = (const float*)d_in[11];
    const float* lin_b   = (const float*)d_in[12];
    float* out = (float*)d_out;

    k1_proj<<<NSEQ * 256, 288>>>(x, Win, dt_bias, A_log);
    k2_conv<<<NSEQ * 256, 256>>>(conv_w, conv_b);
    k3_scan<<<NSEQ * NCHUNK * 2 / 4, 128>>>();
    k4a_segscan<<<NSEQ * NH * 4, 256>>>();
    k4b_combine<<<NSEQ, 1024>>>();
    k5_fused<<<NSEQ * NCHUNK, 1024>>>(Dp, Wout, norm_w);
    k6a_bnstats<<<3 * 64, 256>>>();
    k6b_coef<<<1, 64>>>(gamma, beta, lin_w, lin_b);
    k7_pool<<<NSEQ * 256, 32>>>(out);
}

// round 15
// speedup vs baseline: 1.5739x; 1.5739x over previous
#include <cuda_runtime.h>
#include <math.h>

#define NSEQ   24
#define LSEQ   8192
#define NCHUNK 128
#define CIN    16
#define DIN    64
#define NH     16
#define HD     4
#define DSTATE 64
#define CONVDIM 192
#define DPROJ  272

// ---------------- scratch ----------------
__device__ float  g_z     [NSEQ*LSEQ*DIN];
__device__ float  g_xBCp  [NSEQ*LSEQ*CONVDIM];
__device__ float  g_xBC   [NSEQ*LSEQ*CONVDIM];   // [0:64]=xh [64:128]=B [128:192]=C
__device__ float2 g_dtA   [NSEQ*LSEQ*NH];        // (dt, dA)
__device__ float  g_ylocal[NSEQ*LSEQ*DIN];
__device__ float  g_cumdec[NSEQ*LSEQ*NH];
__device__ float  g_T     [NSEQ*NCHUNK*4096];
__device__ float  g_Sprev [NSEQ*NCHUNK*4096];    // segment-LOCAL entering states
__device__ float  g_segend[NSEQ*4*4096];         // segment-end local states
__device__ float  g_entry [NSEQ*4*4096];         // global state entering each segment
__device__ float  g_prefix[NSEQ*NCHUNK*NH];      // prod of chunk decays from seg start to ck-1
__device__ float  g_v     [NSEQ*LSEQ*CIN];
__device__ float  g_bnpart[3*64*32];
__device__ float  g_coefw [3*CIN];
__device__ float  g_coefc [3];

__device__ __forceinline__ float silu_f(float x) { return x / (1.f + expf(-x)); }

typedef unsigned long long u64t;
__device__ __forceinline__ u64t pack2(float a, float b) {
    u64t r; asm("mov.b64 %0, {%1,%2};" : "=l"(r) : "f"(a), "f"(b)); return r;
}
__device__ __forceinline__ float2 unpack2(u64t v) {
    float2 f; asm("mov.b64 {%0,%1}, %2;" : "=f"(f.x), "=f"(f.y) : "l"(v)); return f;
}
#define FMA2(d,a,b,c) asm("fma.rn.f32x2 %0,%1,%2,%3;" : "=l"(d) : "l"(a), "l"(b), "l"(c))
#define MUL2(d,a,b)   asm("mul.rn.f32x2 %0,%1,%2;"    : "=l"(d) : "l"(a), "l"(b))

// ---------------- K1: input gather + in-projection (272x16) ----------------
__global__ void k1_proj(const float* __restrict__ x, const float* __restrict__ Win,
                        const float* __restrict__ dt_bias, const float* __restrict__ A_log) {
    int blk  = blockIdx.x;
    int seq  = blk >> 8;
    int tile = blk & 255;
    int dir  = seq / 8, b = seq % 8;
    int l0   = tile * 32;
    int tid  = threadIdx.x;

    __shared__ __align__(16) float us[32 * 16];

    for (int i = tid; i < 512; i += 288) {
        int c = i >> 5, tok = i & 31;
        int l = l0 + tok;
        int xl;
        if (dir == 0) {
            xl = l;
        } else if (dir == 1) {
            int dd = l & 31, ww = (l >> 5) & 15, hh = l >> 9;
            xl = dd * 256 + hh * 16 + ww;
        } else {
            int hh = l & 15, dd = (l >> 4) & 31, ww = l >> 9;
            xl = dd * 256 + hh * 16 + ww;
        }
        us[tok * 16 + c] = x[(b * 16 + c) * 8192 + xl];
    }
    __syncthreads();

    int f = tid;
    if (f >= 272) return;

    float w[16];
    {
        const float4* W4 = reinterpret_cast<const float4*>(Win + (dir * 272 + f) * 16);
        #pragma unroll
        for (int q = 0; q < 4; q++) {
            float4 t = W4[q];
            w[q*4+0] = t.x; w[q*4+1] = t.y; w[q*4+2] = t.z; w[q*4+3] = t.w;
        }
    }
    float dtb = 0.f, Aneg = 0.f;
    if (f >= 256) {
        int h = f - 256;
        dtb  = dt_bias[dir * 16 + h];
        Aneg = -expf(A_log[dir * 16 + h]);
    }

    for (int tok = 0; tok < 32; tok++) {
        const float4* u4 = reinterpret_cast<const float4*>(us + tok * 16);
        float acc = 0.f;
        #pragma unroll
        for (int q = 0; q < 4; q++) {
            float4 t = u4[q];
            acc += t.x * w[q*4+0] + t.y * w[q*4+1] + t.z * w[q*4+2] + t.w * w[q*4+3];
        }
        int bl = seq * LSEQ + (l0 + tok);
        if (f < 64) {
            g_z[bl * 64 + f] = acc;
        } else if (f < 256) {
            g_xBCp[bl * 192 + (f - 64)] = acc;
        } else {
            int h = f - 256;
            float v  = acc + dtb;
            float dt = fmaxf(v, 0.f) + log1pf(expf(-fabsf(v)));
            g_dtA[bl * 16 + h] = make_float2(dt, expf(dt * Aneg));
        }
    }
}

// ---------------- K2: causal depthwise conv (k=4) + SiLU, smem-tiled ----------------
__global__ void k2_conv(const float* __restrict__ conv_w, const float* __restrict__ conv_b) {
    int blk  = blockIdx.x;
    int seq  = blk >> 8;
    int tile = blk & 255;
    int dir  = seq / 8;
    int l0   = tile * 32;
    int tid  = threadIdx.x;

    __shared__ float s[35 * 192];

    for (int i = tid; i < 35 * 192; i += 256) {
        int r = i / 192, ch = i - r * 192;
        int l = l0 - 3 + r;
        s[i] = (l >= 0) ? g_xBCp[(seq * LSEQ + l) * 192 + ch] : 0.f;
    }
    __syncthreads();

    for (int i = tid; i < 32 * 192; i += 256) {
        int tok = i / 192, ch = i - tok * 192;
        float4 w = *reinterpret_cast<const float4*>(conv_w + (dir * 192 + ch) * 4);
        float acc = conv_b[dir * 192 + ch]
                  + s[(tok    ) * 192 + ch] * w.x
                  + s[(tok + 1) * 192 + ch] * w.y
                  + s[(tok + 2) * 192 + ch] * w.z
                  + s[(tok + 3) * 192 + ch] * w.w;
        g_xBC[(seq * LSEQ + l0 + tok) * 192 + ch] = silu_f(acc);
    }
}

// ---------------- K3: chunk-local scan, 8 lanes/head, 8 states/lane (R6 shape + dtA) ----------------
__global__ void k3_scan() {
    int gw    = (blockIdx.x * blockDim.x + threadIdx.x) >> 5;
    int lane  = threadIdx.x & 31;
    int hg    = gw & 3;
    int chunk = (gw >> 2) & 127;
    int seq   = gw >> 9;
    if (seq >= NSEQ) return;

    int li = lane & 7;
    int h  = hg * 4 + (lane >> 3);
    int n0 = li * 8;

    u64t S2[4][4];
    #pragma unroll
    for (int p = 0; p < 4; p++)
        #pragma unroll
        for (int j = 0; j < 4; j++) S2[p][j] = 0ull;
    float cum = 1.f;

    int lbase = seq * LSEQ + chunk * 64;
    #pragma unroll 2
    for (int t = 0; t < 64; t++) {
        int bl = lbase + t;
        float2 dta = g_dtA[bl * 16 + h];       // (dt, dA) one LDG.64
        cum *= dta.y;
        float4 xh4 = *reinterpret_cast<const float4*>(g_xBC + bl * 192 + h * 4);
        ulonglong2 bu0 = *reinterpret_cast<const ulonglong2*>(g_xBC + bl * 192 + 64 + n0);
        ulonglong2 cu0 = *reinterpret_cast<const ulonglong2*>(g_xBC + bl * 192 + 128 + n0);
        u64t B2[4] = { bu0.x, bu0.y, 0, 0 };
        u64t C2[4] = { cu0.x, cu0.y, 0, 0 };
        {
            ulonglong2 bu1 = *reinterpret_cast<const ulonglong2*>(g_xBC + bl * 192 + 64 + n0 + 4);
            ulonglong2 cu1 = *reinterpret_cast<const ulonglong2*>(g_xBC + bl * 192 + 128 + n0 + 4);
            B2[2] = bu1.x; B2[3] = bu1.y;
            C2[2] = cu1.x; C2[3] = cu1.y;
        }

        u64t dA2 = pack2(dta.y, dta.y);
        float xh[4] = { xh4.x, xh4.y, xh4.z, xh4.w };
        u64t dtx2[4];
        #pragma unroll
        for (int p = 0; p < 4; p++) {
            float d_ = dta.x * xh[p];
            dtx2[p] = pack2(d_, d_);
        }

        float acc[4];
        #pragma unroll
        for (int p = 0; p < 4; p++) {
            u64t a, tp;
            MUL2(tp, dtx2[p], B2[0]);
            FMA2(S2[p][0], S2[p][0], dA2, tp);
            MUL2(a, S2[p][0], C2[0]);
            #pragma unroll
            for (int j = 1; j < 4; j++) {
                MUL2(tp, dtx2[p], B2[j]);
                FMA2(S2[p][j], S2[p][j], dA2, tp);
                FMA2(a, S2[p][j], C2[j], a);
            }
            float2 f = unpack2(a);
            acc[p] = f.x + f.y;
        }
        #pragma unroll
        for (int off = 4; off >= 1; off >>= 1) {
            #pragma unroll
            for (int p = 0; p < 4; p++)
                acc[p] += __shfl_xor_sync(0xffffffffu, acc[p], off);
        }
        if (li == 0) {
            *reinterpret_cast<float4*>(g_ylocal + bl * 64 + h * 4) =
                make_float4(acc[0], acc[1], acc[2], acc[3]);
            g_cumdec[bl * 16 + h] = cum;
        }
    }
    int tb = (seq * 128 + chunk) * 4096 + h * 256;
    #pragma unroll
    for (int p = 0; p < 4; p++) {
        ulonglong2 v0; v0.x = S2[p][0]; v0.y = S2[p][1];
        ulonglong2 v1; v1.x = S2[p][2]; v1.y = S2[p][3];
        *reinterpret_cast<ulonglong2*>(g_T + tb + p * 64 + n0)     = v0;
        *reinterpret_cast<ulonglong2*>(g_T + tb + p * 64 + n0 + 4) = v1;
    }
}

// ---------------- K4a: segment-local state scans (fully parallel) ----------------
__global__ void k4a_segscan() {
    int b    = blockIdx.x;
    int seq  = b >> 6;
    int rem  = b & 63;
    int h    = rem >> 2;
    int seg  = rem & 3;
    int elem = h * 256 + threadIdx.x;

    __shared__ float dec[32];
    if (threadIdx.x < 32)
        dec[threadIdx.x] = g_cumdec[(seq * LSEQ + (seg * 32 + threadIdx.x) * 64 + 63) * 16 + h];
    __syncthreads();

    int ck0 = seg * 32;
    float S  = 0.f;
    float Tn = g_T[(seq * 128 + ck0) * 4096 + elem];
    #pragma unroll 4
    for (int j = 0; j < 32; j++) {
        int base = (seq * 128 + ck0 + j) * 4096 + elem;
        g_Sprev[base] = S;                     // segment-LOCAL entering state
        float Tc = Tn;
        if (j < 31) Tn = g_T[base + 4096];
        S = fmaf(S, dec[j], Tc);
    }
    g_segend[(seq * 4 + seg) * 4096 + elem] = S;
}

// ---------------- K4b: combine segments + decay prefixes ----------------
__global__ void k4b_combine() {
    int seq = blockIdx.x;
    int tid = threadIdx.x;
    __shared__ float DECs[4][16];

    if (tid < 64) {
        int s = tid >> 4, h = tid & 15;
        float p = 1.f;
        for (int j = 0; j < 32; j++) {
            int ck = s * 32 + j;
            g_prefix[(seq * 128 + ck) * 16 + h] = p;
            p *= g_cumdec[(seq * LSEQ + ck * 64 + 63) * 16 + h];
        }
        DECs[s][h] = p;
    }
    __syncthreads();

    int elem = tid * 4;
    int h    = elem >> 8;
    float4 e = make_float4(0.f, 0.f, 0.f, 0.f);
    #pragma unroll
    for (int s = 0; s < 4; s++) {
        *reinterpret_cast<float4*>(g_entry + (seq * 4 + s) * 4096 + elem) = e;
        float4 E = *reinterpret_cast<const float4*>(g_segend + (seq * 4 + s) * 4096 + elem);
        float d = DECs[s][h];
        e.x = e.x * d + E.x;
        e.y = e.y * d + E.y;
        e.z = e.z * d + E.z;
        e.w = e.w * d + E.w;
    }
}

// ---------------- K5: inter-chunk correction + gating + RMSNorm + out-proj + ReLU ----------------
__global__ void __launch_bounds__(1024, 2) k5_fused(const float* __restrict__ Dp,
                                                    const float* __restrict__ Wout,
                                                    const float* __restrict__ norm_w) {
    int bid   = blockIdx.x;
    int seq   = bid >> 7;
    int chunk = bid & 127;
    int dir   = seq / 8;
    int tid   = threadIdx.x;
    int h     = tid >> 6;
    int t     = tid & 63;

    __shared__ __align__(16) float Sp[4096];
    __shared__ float CsY[64 * 65];
    __shared__ float ssq[1024];
    __shared__ __align__(16) float Ws[1024];
    __shared__ float nww[64];

    {
        int elem = tid * 4;          // elem>>8 == h for this thread
        float pref = g_prefix[(seq * 128 + chunk) * 16 + h];
        float4 sv = *reinterpret_cast<const float4*>(g_Sprev + (seq * 128 + chunk) * 4096 + elem);
        float4 ev = *reinterpret_cast<const float4*>(g_entry + (seq * 4 + (chunk >> 5)) * 4096 + elem);
        Sp[elem + 0] = fmaf(pref, ev.x, sv.x);
        Sp[elem + 1] = fmaf(pref, ev.y, sv.y);
        Sp[elem + 2] = fmaf(pref, ev.z, sv.z);
        Sp[elem + 3] = fmaf(pref, ev.w, sv.w);
    }
    {
        int flat = tid * 4;
        int tr = flat >> 6, nc = flat & 63;
        float4 v = *reinterpret_cast<const float4*>(
            g_xBC + (seq * LSEQ + chunk * 64 + tr) * 192 + 128 + nc);
        CsY[tr * 65 + nc + 0] = v.x;
        CsY[tr * 65 + nc + 1] = v.y;
        CsY[tr * 65 + nc + 2] = v.z;
        CsY[tr * 65 + nc + 3] = v.w;
    }
    if (tid < 1024) Ws[tid] = Wout[dir * 1024 + tid];
    if (tid < 64)   nww[tid] = norm_w[dir * 64 + tid];
    __syncthreads();

    const float* Sh = Sp + h * 256;
    const float* Ct = CsY + t * 65;
    float a0 = 0.f, a1 = 0.f, a2 = 0.f, a3 = 0.f;
    #pragma unroll 4
    for (int n = 0; n < 64; n += 4) {
        float c0 = Ct[n], c1 = Ct[n + 1], c2 = Ct[n + 2], c3 = Ct[n + 3];
        float4 s;
        s = *reinterpret_cast<const float4*>(Sh + n);        a0 += c0*s.x + c1*s.y + c2*s.z + c3*s.w;
        s = *reinterpret_cast<const float4*>(Sh + 64 + n);   a1 += c0*s.x + c1*s.y + c2*s.z + c3*s.w;
        s = *reinterpret_cast<const float4*>(Sh + 128 + n);  a2 += c0*s.x + c1*s.y + c2*s.z + c3*s.w;
        s = *reinterpret_cast<const float4*>(Sh + 192 + n);  a3 += c0*s.x + c1*s.y + c2*s.z + c3*s.w;
    }

    int bl = seq * LSEQ + chunk * 64 + t;
    float cd   = g_cumdec[bl * 16 + h];
    float4 yl  = *reinterpret_cast<const float4*>(g_ylocal + bl * 64 + h * 4);
    float4 xh  = *reinterpret_cast<const float4*>(g_xBC + bl * 192 + h * 4);
    float4 z4  = *reinterpret_cast<const float4*>(g_z + bl * 64 + h * 4);
    float dp   = Dp[dir * 16 + h];

    float o0 = (yl.x + cd * a0 + dp * xh.x) * silu_f(z4.x);
    float o1 = (yl.y + cd * a1 + dp * xh.y) * silu_f(z4.y);
    float o2 = (yl.z + cd * a2 + dp * xh.z) * silu_f(z4.z);
    float o3 = (yl.w + cd * a3 + dp * xh.w) * silu_f(z4.w);

    ssq[tid] = o0*o0 + o1*o1 + o2*o2 + o3*o3;
    __syncthreads();

    float ss = 0.f;
    #pragma unroll
    for (int hh = 0; hh < 16; hh++) ss += ssq[hh * 64 + t];
    float scale = rsqrtf(ss * (1.f / 64.f) + 1e-5f);

    CsY[(h * 4 + 0) * 65 + t] = o0 * scale * nww[h * 4 + 0];
    CsY[(h * 4 + 1) * 65 + t] = o1 * scale * nww[h * 4 + 1];
    CsY[(h * 4 + 2) * 65 + t] = o2 * scale * nww[h * 4 + 2];
    CsY[(h * 4 + 3) * 65 + t] = o3 * scale * nww[h * 4 + 3];
    __syncthreads();

    float acc = 0.f;
    const float4* w4 = reinterpret_cast<const float4*>(Ws + h * 64);
    #pragma unroll 4
    for (int d = 0; d < 64; d += 4) {
        float4 w = w4[d >> 2];
        acc += CsY[(d    ) * 65 + t] * w.x
             + CsY[(d + 1) * 65 + t] * w.y
             + CsY[(d + 2) * 65 + t] * w.z
             + CsY[(d + 3) * 65 + t] * w.w;
    }
    g_v[bl * 16 + h] = fmaxf(acc, 0.f);
}

// ---------------- K6a/K6b: deterministic BN statistics + folded coefficients ----------------
__global__ void k6a_bnstats() {
    int dir = blockIdx.x >> 6;
    int blk = blockIdx.x & 63;
    int tid = threadIdx.x;

    float sum[16], sq[16];
    #pragma unroll
    for (int c = 0; c < 16; c++) { sum[c] = 0.f; sq[c] = 0.f; }

    int rowbase = dir * 65536 + blk * 1024;
    for (int r = tid; r < 1024; r += 256) {
        const float4* v4 = reinterpret_cast<const float4*>(g_v + (rowbase + r) * 16);
        #pragma unroll
        for (int q = 0; q < 4; q++) {
            float4 v = v4[q];
            sum[q*4+0] += v.x; sq[q*4+0] += v.x*v.x;
            sum[q*4+1] += v.y; sq[q*4+1] += v.y*v.y;
            sum[q*4+2] += v.z; sq[q*4+2] += v.z*v.z;
            sum[q*4+3] += v.w; sq[q*4+3] += v.w*v.w;
        }
    }
    __shared__ float red[256 * 32];
    #pragma unroll
    for (int c = 0; c < 16; c++) {
        red[tid * 32 + c]      = sum[c];
        red[tid * 32 + 16 + c] = sq[c];
    }
    __syncthreads();
    if (tid < 32) {
        float tot = 0.f;
        for (int r = 0; r < 256; r++) tot += red[r * 32 + tid];
        g_bnpart[(dir * 64 + blk) * 32 + tid] = tot;
    }
}

__global__ void k6b_coef(const float* __restrict__ gamma, const float* __restrict__ beta,
                         const float* __restrict__ lin_w, const float* __restrict__ lin_b) {
    int tid = threadIdx.x;
    __shared__ float cpart[3][16];
    if (tid < 48) {
        int dir = tid / 16, c = tid % 16;
        float s = 0.f, q = 0.f;
        for (int blk = 0; blk < 64; blk++) {
            s += g_bnpart[(dir * 64 + blk) * 32 + c];
            q += g_bnpart[(dir * 64 + blk) * 32 + 16 + c];
        }
        float mu  = s * (1.f / 65536.f);
        float var = q * (1.f / 65536.f) - mu * mu;
        float inv = rsqrtf(var + 1e-5f);
        float g  = gamma[dir * 16 + c];
        float bt = beta[dir * 16 + c];
        float lw = lin_w[dir * 16 + c];
        g_coefw[dir * 16 + c] = inv * g * lw;
        cpart[dir][c] = (bt - mu * inv * g) * lw;
    }
    __syncthreads();
    if (tid < 3) {
        float s = lin_b[tid];
        for (int c = 0; c < 16; c++) s += cpart[tid][c];
        g_coefc[tid] = s;
    }
}

// ---------------- K7: linear + adaptive max pool ----------------
__global__ void k7_pool(float* __restrict__ out) {
    int bid  = blockIdx.x;
    int seq  = bid >> 8;
    int pool = bid & 255;
    int dir  = seq / 8, b = seq % 8;
    int lane = threadIdx.x;

    float4 cw0 = *reinterpret_cast<const float4*>(g_coefw + dir * 16);
    float4 cw1 = *reinterpret_cast<const float4*>(g_coefw + dir * 16 + 4);
    float4 cw2 = *reinterpret_cast<const float4*>(g_coefw + dir * 16 + 8);
    float4 cw3 = *reinterpret_cast<const float4*>(g_coefw + dir * 16 + 12);

    int bl = seq * LSEQ + pool * 32 + lane;
    const float4* v4 = reinterpret_cast<const float4*>(g_v + bl * 16);
    float s = g_coefc[dir];
    float4 v;
    v = v4[0]; s += v.x*cw0.x + v.y*cw0.y + v.z*cw0.z + v.w*cw0.w;
    v = v4[1]; s += v.x*cw1.x + v.y*cw1.y + v.z*cw1.z + v.w*cw1.w;
    v = v4[2]; s += v.x*cw2.x + v.y*cw2.y + v.z*cw2.z + v.w*cw2.w;
    v = v4[3]; s += v.x*cw3.x + v.y*cw3.y + v.z*cw3.z + v.w*cw3.w;

    #pragma unroll
    for (int off = 16; off >= 1; off >>= 1)
        s = fmaxf(s, __shfl_xor_sync(0xffffffffu, s, off));
    if (lane == 0) out[b * 768 + dir * 256 + pool] = s;
}

// ---------------- launch ----------------
extern "C" void kernel_launch(void* const* d_in, const int* in_sizes, int n_in,
                              void* d_out, int out_size) {
    const float* x       = (const float*)d_in[0];
    const float* Win     = (const float*)d_in[1];
    const float* conv_w  = (const float*)d_in[2];
    const float* conv_b  = (const float*)d_in[3];
    const float* dt_bias = (const float*)d_in[4];
    const float* A_log   = (const float*)d_in[5];
    const float* Dp      = (const float*)d_in[6];
    const float* norm_w  = (const float*)d_in[7];
    const float* Wout    = (const float*)d_in[8];
    const float* gamma   = (const float*)d_in[9];
    const float* beta    = (const float*)d_in[10];
    const float* lin_w   = (const float*)d_in[11];
    const float* lin_b   = (const float*)d_in[12];
    float* out = (float*)d_out;

    k1_proj<<<NSEQ * 256, 288>>>(x, Win, dt_bias, A_log);
    k2_conv<<<NSEQ * 256, 256>>>(conv_w, conv_b);
    k3_scan<<<(NSEQ * NCHUNK * 4) / 8, 256>>>();
    k4a_segscan<<<NSEQ * NH * 4, 256>>>();
    k4b_combine<<<NSEQ, 1024>>>();
    k5_fused<<<NSEQ * NCHUNK, 1024>>>(Dp, Wout, norm_w);
    k6a_bnstats<<<3 * 64, 256>>>();
    k6b_coef<<<1, 64>>>(gamma, beta, lin_w, lin_b);
    k7_pool<<<NSEQ * 256, 32>>>(out);
}

// round 17
// speedup vs baseline: 1.7505x; 1.1122x over previous
#include <cuda_runtime.h>
#include <math.h>

#define NSEQ   24
#define LSEQ   8192
#define NCHUNK 128
#define CIN    16
#define DIN    64
#define NH     16
#define HD     4
#define DSTATE 64
#define CONVDIM 192
#define DPROJ  272

// ---------------- scratch ----------------
__device__ float  g_z     [NSEQ*LSEQ*DIN];
__device__ float  g_xBC   [NSEQ*LSEQ*CONVDIM];   // [0:64]=xh [64:128]=B [128:192]=C
__device__ float2 g_dtA   [NSEQ*LSEQ*NH];        // (dt, dA)
__device__ float  g_ylocal[NSEQ*LSEQ*DIN];
__device__ float  g_cumdec[NSEQ*LSEQ*NH];
__device__ float  g_T     [NSEQ*NCHUNK*4096];
__device__ float  g_Sprev [NSEQ*NCHUNK*4096];    // segment-LOCAL entering states
__device__ float  g_segend[NSEQ*4*4096];
__device__ float  g_entry [NSEQ*4*4096];
__device__ float  g_prefix[NSEQ*NCHUNK*NH];
__device__ float  g_v     [NSEQ*LSEQ*CIN];
__device__ float  g_bnpart[3*64*32];
__device__ float  g_coefw [3*CIN];
__device__ float  g_coefc [3];

__device__ __forceinline__ float silu_f(float x) { return x / (1.f + expf(-x)); }

typedef unsigned long long u64t;
__device__ __forceinline__ u64t pack2(float a, float b) {
    u64t r; asm("mov.b64 %0, {%1,%2};" : "=l"(r) : "f"(a), "f"(b)); return r;
}
__device__ __forceinline__ float2 unpack2(u64t v) {
    float2 f; asm("mov.b64 {%0,%1}, %2;" : "=f"(f.x), "=f"(f.y) : "l"(v)); return f;
}
#define FMA2(d,a,b,c) asm("fma.rn.f32x2 %0,%1,%2,%3;" : "=l"(d) : "l"(a), "l"(b), "l"(c))
#define MUL2(d,a,b)   asm("mul.rn.f32x2 %0,%1,%2;"    : "=l"(d) : "l"(a), "l"(b))

// ---------------- K12: fused in-projection + causal conv + SiLU ----------------
// block = 288 threads, 32 output tokens per block; conv-halo (3 tokens) recomputed locally.
__global__ void k12_fused(const float* __restrict__ x, const float* __restrict__ Win,
                          const float* __restrict__ dt_bias, const float* __restrict__ A_log,
                          const float* __restrict__ conv_w, const float* __restrict__ conv_b) {
    int blk  = blockIdx.x;
    int seq  = blk >> 8;
    int tile = blk & 255;
    int dir  = seq / 8, b = seq % 8;
    int l0   = tile * 32;
    int tid  = threadIdx.x;

    __shared__ __align__(16) float us[35 * 16];     // tokens l0-3 .. l0+31
    __shared__ float xt[35 * 192];                  // pre-conv xBC tile [tok][ch]

    // gather 35 tokens (3-token halo before l0)
    for (int i = tid; i < 35 * 16; i += 288) {
        int tok = i >> 4, c = i & 15;
        int l = l0 - 3 + tok;
        float v = 0.f;
        if (l >= 0) {
            int xl;
            if (dir == 0) {
                xl = l;
            } else if (dir == 1) {
                int dd = l & 31, ww = (l >> 5) & 15, hh = l >> 9;
                xl = dd * 256 + hh * 16 + ww;
            } else {
                int hh = l & 15, dd = (l >> 4) & 31, ww = l >> 9;
                xl = dd * 256 + hh * 16 + ww;
            }
            v = x[(b * 16 + c) * 8192 + xl];
        }
        us[tok * 16 + c] = v;
    }
    __syncthreads();

    int f = tid;
    if (f < 272) {
        float w[16];
        {
            const float4* W4 = reinterpret_cast<const float4*>(Win + (dir * 272 + f) * 16);
            #pragma unroll
            for (int q = 0; q < 4; q++) {
                float4 t = W4[q];
                w[q*4+0] = t.x; w[q*4+1] = t.y; w[q*4+2] = t.z; w[q*4+3] = t.w;
            }
        }

        if (f >= 64 && f < 256) {
            // conv-path features: project 35 tokens into smem tile
            int ch = f - 64;
            for (int tok = 0; tok < 35; tok++) {
                const float4* u4 = reinterpret_cast<const float4*>(us + tok * 16);
                float acc = 0.f;
                #pragma unroll
                for (int q = 0; q < 4; q++) {
                    float4 t = u4[q];
                    acc += t.x * w[q*4+0] + t.y * w[q*4+1] + t.z * w[q*4+2] + t.w * w[q*4+3];
                }
                xt[tok * 192 + ch] = acc;
            }
        } else if (f < 64) {
            for (int tok = 0; tok < 32; tok++) {
                const float4* u4 = reinterpret_cast<const float4*>(us + (tok + 3) * 16);
                float acc = 0.f;
                #pragma unroll
                for (int q = 0; q < 4; q++) {
                    float4 t = u4[q];
                    acc += t.x * w[q*4+0] + t.y * w[q*4+1] + t.z * w[q*4+2] + t.w * w[q*4+3];
                }
                g_z[(seq * LSEQ + l0 + tok) * 64 + f] = acc;
            }
        } else {
            int h = f - 256;
            float dtb  = dt_bias[dir * 16 + h];
            float Aneg = -expf(A_log[dir * 16 + h]);
            for (int tok = 0; tok < 32; tok++) {
                const float4* u4 = reinterpret_cast<const float4*>(us + (tok + 3) * 16);
                float acc = 0.f;
                #pragma unroll
                for (int q = 0; q < 4; q++) {
                    float4 t = u4[q];
                    acc += t.x * w[q*4+0] + t.y * w[q*4+1] + t.z * w[q*4+2] + t.w * w[q*4+3];
                }
                float v  = acc + dtb;
                float dt = fmaxf(v, 0.f) + log1pf(expf(-fabsf(v)));
                g_dtA[(seq * LSEQ + l0 + tok) * 16 + h] = make_float2(dt, expf(dt * Aneg));
            }
        }
    }
    __syncthreads();

    // conv k=4 + SiLU from smem tile; output token l0+tok uses rows tok..tok+3
    for (int i = tid; i < 32 * 192; i += 288) {
        int tok = i / 192, ch = i - tok * 192;
        float4 w = *reinterpret_cast<const float4*>(conv_w + (dir * 192 + ch) * 4);
        float acc = conv_b[dir * 192 + ch]
                  + xt[(tok    ) * 192 + ch] * w.x
                  + xt[(tok + 1) * 192 + ch] * w.y
                  + xt[(tok + 2) * 192 + ch] * w.z
                  + xt[(tok + 3) * 192 + ch] * w.w;
        g_xBC[(seq * LSEQ + l0 + tok) * 192 + ch] = silu_f(acc);
    }
}

// ---------------- K3: chunk-local scan, 8 lanes/head, 8 states/lane ----------------
__global__ void k3_scan() {
    int gw    = (blockIdx.x * blockDim.x + threadIdx.x) >> 5;
    int lane  = threadIdx.x & 31;
    int hg    = gw & 3;
    int chunk = (gw >> 2) & 127;
    int seq   = gw >> 9;
    if (seq >= NSEQ) return;

    int li = lane & 7;
    int h  = hg * 4 + (lane >> 3);
    int n0 = li * 8;

    u64t S2[4][4];
    #pragma unroll
    for (int p = 0; p < 4; p++)
        #pragma unroll
        for (int j = 0; j < 4; j++) S2[p][j] = 0ull;
    float cum = 1.f;

    int lbase = seq * LSEQ + chunk * 64;
    #pragma unroll 2
    for (int t = 0; t < 64; t++) {
        int bl = lbase + t;
        float2 dta = g_dtA[bl * 16 + h];
        cum *= dta.y;
        float4 xh4 = *reinterpret_cast<const float4*>(g_xBC + bl * 192 + h * 4);
        ulonglong2 bu0 = *reinterpret_cast<const ulonglong2*>(g_xBC + bl * 192 + 64 + n0);
        ulonglong2 cu0 = *reinterpret_cast<const ulonglong2*>(g_xBC + bl * 192 + 128 + n0);
        u64t B2[4] = { bu0.x, bu0.y, 0, 0 };
        u64t C2[4] = { cu0.x, cu0.y, 0, 0 };
        {
            ulonglong2 bu1 = *reinterpret_cast<const ulonglong2*>(g_xBC + bl * 192 + 64 + n0 + 4);
            ulonglong2 cu1 = *reinterpret_cast<const ulonglong2*>(g_xBC + bl * 192 + 128 + n0 + 4);
            B2[2] = bu1.x; B2[3] = bu1.y;
            C2[2] = cu1.x; C2[3] = cu1.y;
        }

        u64t dA2 = pack2(dta.y, dta.y);
        float xh[4] = { xh4.x, xh4.y, xh4.z, xh4.w };
        u64t dtx2[4];
        #pragma unroll
        for (int p = 0; p < 4; p++) {
            float d_ = dta.x * xh[p];
            dtx2[p] = pack2(d_, d_);
        }

        float acc[4];
        #pragma unroll
        for (int p = 0; p < 4; p++) {
            u64t a, tp;
            MUL2(tp, dtx2[p], B2[0]);
            FMA2(S2[p][0], S2[p][0], dA2, tp);
            MUL2(a, S2[p][0], C2[0]);
            #pragma unroll
            for (int j = 1; j < 4; j++) {
                MUL2(tp, dtx2[p], B2[j]);
                FMA2(S2[p][j], S2[p][j], dA2, tp);
                FMA2(a, S2[p][j], C2[j], a);
            }
            float2 f = unpack2(a);
            acc[p] = f.x + f.y;
        }
        #pragma unroll
        for (int off = 4; off >= 1; off >>= 1) {
            #pragma unroll
            for (int p = 0; p < 4; p++)
                acc[p] += __shfl_xor_sync(0xffffffffu, acc[p], off);
        }
        if (li == 0) {
            *reinterpret_cast<float4*>(g_ylocal + bl * 64 + h * 4) =
                make_float4(acc[0], acc[1], acc[2], acc[3]);
            g_cumdec[bl * 16 + h] = cum;
        }
    }
    int tb = (seq * 128 + chunk) * 4096 + h * 256;
    #pragma unroll
    for (int p = 0; p < 4; p++) {
        ulonglong2 v0; v0.x = S2[p][0]; v0.y = S2[p][1];
        ulonglong2 v1; v1.x = S2[p][2]; v1.y = S2[p][3];
        *reinterpret_cast<ulonglong2*>(g_T + tb + p * 64 + n0)     = v0;
        *reinterpret_cast<ulonglong2*>(g_T + tb + p * 64 + n0 + 4) = v1;
    }
}

// ---------------- K4a: segment-local state scans ----------------
__global__ void k4a_segscan() {
    int b    = blockIdx.x;
    int seq  = b >> 6;
    int rem  = b & 63;
    int h    = rem >> 2;
    int seg  = rem & 3;
    int elem = h * 256 + threadIdx.x;

    __shared__ float dec[32];
    if (threadIdx.x < 32)
        dec[threadIdx.x] = g_cumdec[(seq * LSEQ + (seg * 32 + threadIdx.x) * 64 + 63) * 16 + h];
    __syncthreads();

    int ck0 = seg * 32;
    float S  = 0.f;
    float Tn = g_T[(seq * 128 + ck0) * 4096 + elem];
    #pragma unroll 4
    for (int j = 0; j < 32; j++) {
        int base = (seq * 128 + ck0 + j) * 4096 + elem;
        g_Sprev[base] = S;
        float Tc = Tn;
        if (j < 31) Tn = g_T[base + 4096];
        S = fmaf(S, dec[j], Tc);
    }
    g_segend[(seq * 4 + seg) * 4096 + elem] = S;
}

// ---------------- K4b: combine segments + decay prefixes ----------------
__global__ void k4b_combine() {
    int seq = blockIdx.x;
    int tid = threadIdx.x;
    __shared__ float DECs[4][16];

    if (tid < 64) {
        int s = tid >> 4, h = tid & 15;
        float p = 1.f;
        for (int j = 0; j < 32; j++) {
            int ck = s * 32 + j;
            g_prefix[(seq * 128 + ck) * 16 + h] = p;
            p *= g_cumdec[(seq * LSEQ + ck * 64 + 63) * 16 + h];
        }
        DECs[s][h] = p;
    }
    __syncthreads();

    int elem = tid * 4;
    int h    = elem >> 8;
    float4 e = make_float4(0.f, 0.f, 0.f, 0.f);
    #pragma unroll
    for (int s = 0; s < 4; s++) {
        *reinterpret_cast<float4*>(g_entry + (seq * 4 + s) * 4096 + elem) = e;
        float4 E = *reinterpret_cast<const float4*>(g_segend + (seq * 4 + s) * 4096 + elem);
        float d = DECs[s][h];
        e.x = e.x * d + E.x;
        e.y = e.y * d + E.y;
        e.z = e.z * d + E.z;
        e.w = e.w * d + E.w;
    }
}

// ---------------- K5: inter-chunk correction + gating + RMSNorm + out-proj + ReLU ----------------
__global__ void __launch_bounds__(1024, 2) k5_fused(const float* __restrict__ Dp,
                                                    const float* __restrict__ Wout,
                                                    const float* __restrict__ norm_w) {
    int bid   = blockIdx.x;
    int seq   = bid >> 7;
    int chunk = bid & 127;
    int dir   = seq / 8;
    int tid   = threadIdx.x;
    int h     = tid >> 6;
    int t     = tid & 63;

    __shared__ __align__(16) float Sp[4096];
    __shared__ float CsY[64 * 65];
    __shared__ float ssq[1024];
    __shared__ __align__(16) float Ws[1024];
    __shared__ float nww[64];

    {
        int elem = tid * 4;
        float pref = g_prefix[(seq * 128 + chunk) * 16 + h];
        float4 sv = *reinterpret_cast<const float4*>(g_Sprev + (seq * 128 + chunk) * 4096 + elem);
        float4 ev = *reinterpret_cast<const float4*>(g_entry + (seq * 4 + (chunk >> 5)) * 4096 + elem);
        Sp[elem + 0] = fmaf(pref, ev.x, sv.x);
        Sp[elem + 1] = fmaf(pref, ev.y, sv.y);
        Sp[elem + 2] = fmaf(pref, ev.z, sv.z);
        Sp[elem + 3] = fmaf(pref, ev.w, sv.w);
    }
    {
        int flat = tid * 4;
        int tr = flat >> 6, nc = flat & 63;
        float4 v = *reinterpret_cast<const float4*>(
            g_xBC + (seq * LSEQ + chunk * 64 + tr) * 192 + 128 + nc);
        CsY[tr * 65 + nc + 0] = v.x;
        CsY[tr * 65 + nc + 1] = v.y;
        CsY[tr * 65 + nc + 2] = v.z;
        CsY[tr * 65 + nc + 3] = v.w;
    }
    if (tid < 1024) Ws[tid] = Wout[dir * 1024 + tid];
    if (tid < 64)   nww[tid] = norm_w[dir * 64 + tid];
    __syncthreads();

    const float* Sh = Sp + h * 256;
    const float* Ct = CsY + t * 65;
    float a0 = 0.f, a1 = 0.f, a2 = 0.f, a3 = 0.f;
    #pragma unroll 4
    for (int n = 0; n < 64; n += 4) {
        float c0 = Ct[n], c1 = Ct[n + 1], c2 = Ct[n + 2], c3 = Ct[n + 3];
        float4 s;
        s = *reinterpret_cast<const float4*>(Sh + n);        a0 += c0*s.x + c1*s.y + c2*s.z + c3*s.w;
        s = *reinterpret_cast<const float4*>(Sh + 64 + n);   a1 += c0*s.x + c1*s.y + c2*s.z + c3*s.w;
        s = *reinterpret_cast<const float4*>(Sh + 128 + n);  a2 += c0*s.x + c1*s.y + c2*s.z + c3*s.w;
        s = *reinterpret_cast<const float4*>(Sh + 192 + n);  a3 += c0*s.x + c1*s.y + c2*s.z + c3*s.w;
    }

    int bl = seq * LSEQ + chunk * 64 + t;
    float cd   = g_cumdec[bl * 16 + h];
    float4 yl  = *reinterpret_cast<const float4*>(g_ylocal + bl * 64 + h * 4);
    float4 xh  = *reinterpret_cast<const float4*>(g_xBC + bl * 192 + h * 4);
    float4 z4  = *reinterpret_cast<const float4*>(g_z + bl * 64 + h * 4);
    float dp   = Dp[dir * 16 + h];

    float o0 = (yl.x + cd * a0 + dp * xh.x) * silu_f(z4.x);
    float o1 = (yl.y + cd * a1 + dp * xh.y) * silu_f(z4.y);
    float o2 = (yl.z + cd * a2 + dp * xh.z) * silu_f(z4.z);
    float o3 = (yl.w + cd * a3 + dp * xh.w) * silu_f(z4.w);

    ssq[tid] = o0*o0 + o1*o1 + o2*o2 + o3*o3;
    __syncthreads();

    float ss = 0.f;
    #pragma unroll
    for (int hh = 0; hh < 16; hh++) ss += ssq[hh * 64 + t];
    float scale = rsqrtf(ss * (1.f / 64.f) + 1e-5f);

    CsY[(h * 4 + 0) * 65 + t] = o0 * scale * nww[h * 4 + 0];
    CsY[(h * 4 + 1) * 65 + t] = o1 * scale * nww[h * 4 + 1];
    CsY[(h * 4 + 2) * 65 + t] = o2 * scale * nww[h * 4 + 2];
    CsY[(h * 4 + 3) * 65 + t] = o3 * scale * nww[h * 4 + 3];
    __syncthreads();

    float acc = 0.f;
    const float4* w4 = reinterpret_cast<const float4*>(Ws + h * 64);
    #pragma unroll 4
    for (int d = 0; d < 64; d += 4) {
        float4 w = w4[d >> 2];
        acc += CsY[(d    ) * 65 + t] * w.x
             + CsY[(d + 1) * 65 + t] * w.y
             + CsY[(d + 2) * 65 + t] * w.z
             + CsY[(d + 3) * 65 + t] * w.w;
    }
    g_v[bl * 16 + h] = fmaxf(acc, 0.f);
}

// ---------------- K6a/K6b: deterministic BN statistics + folded coefficients ----------------
__global__ void k6a_bnstats() {
    int dir = blockIdx.x >> 6;
    int blk = blockIdx.x & 63;
    int tid = threadIdx.x;

    float sum[16], sq[16];
    #pragma unroll
    for (int c = 0; c < 16; c++) { sum[c] = 0.f; sq[c] = 0.f; }

    int rowbase = dir * 65536 + blk * 1024;
    for (int r = tid; r < 1024; r += 256) {
        const float4* v4 = reinterpret_cast<const float4*>(g_v + (rowbase + r) * 16);
        #pragma unroll
        for (int q = 0; q < 4; q++) {
            float4 v = v4[q];
            sum[q*4+0] += v.x; sq[q*4+0] += v.x*v.x;
            sum[q*4+1] += v.y; sq[q*4+1] += v.y*v.y;
            sum[q*4+2] += v.z; sq[q*4+2] += v.z*v.z;
            sum[q*4+3] += v.w; sq[q*4+3] += v.w*v.w;
        }
    }
    __shared__ float red[256 * 32];
    #pragma unroll
    for (int c = 0; c < 16; c++) {
        red[tid * 32 + c]      = sum[c];
        red[tid * 32 + 16 + c] = sq[c];
    }
    __syncthreads();
    if (tid < 32) {
        float tot = 0.f;
        for (int r = 0; r < 256; r++) tot += red[r * 32 + tid];
        g_bnpart[(dir * 64 + blk) * 32 + tid] = tot;
    }
}

__global__ void k6b_coef(const float* __restrict__ gamma, const float* __restrict__ beta,
                         const float* __restrict__ lin_w, const float* __restrict__ lin_b) {
    int tid = threadIdx.x;
    __shared__ float cpart[3][16];
    if (tid < 48) {
        int dir = tid / 16, c = tid % 16;
        float s = 0.f, q = 0.f;
        for (int blk = 0; blk < 64; blk++) {
            s += g_bnpart[(dir * 64 + blk) * 32 + c];
            q += g_bnpart[(dir * 64 + blk) * 32 + 16 + c];
        }
        float mu  = s * (1.f / 65536.f);
        float var = q * (1.f / 65536.f) - mu * mu;
        float inv = rsqrtf(var + 1e-5f);
        float g  = gamma[dir * 16 + c];
        float bt = beta[dir * 16 + c];
        float lw = lin_w[dir * 16 + c];
        g_coefw[dir * 16 + c] = inv * g * lw;
        cpart[dir][c] = (bt - mu * inv * g) * lw;
    }
    __syncthreads();
    if (tid < 3) {
        float s = lin_b[tid];
        for (int c = 0; c < 16; c++) s += cpart[tid][c];
        g_coefc[tid] = s;
    }
}

// ---------------- K7: linear + adaptive max pool ----------------
__global__ void k7_pool(float* __restrict__ out) {
    int bid  = blockIdx.x;
    int seq  = bid >> 8;
    int pool = bid & 255;
    int dir  = seq / 8, b = seq % 8;
    int lane = threadIdx.x;

    float4 cw0 = *reinterpret_cast<const float4*>(g_coefw + dir * 16);
    float4 cw1 = *reinterpret_cast<const float4*>(g_coefw + dir * 16 + 4);
    float4 cw2 = *reinterpret_cast<const float4*>(g_coefw + dir * 16 + 8);
    float4 cw3 = *reinterpret_cast<const float4*>(g_coefw + dir * 16 + 12);

    int bl = seq * LSEQ + pool * 32 + lane;
    const float4* v4 = reinterpret_cast<const float4*>(g_v + bl * 16);
    float s = g_coefc[dir];
    float4 v;
    v = v4[0]; s += v.x*cw0.x + v.y*cw0.y + v.z*cw0.z + v.w*cw0.w;
    v = v4[1]; s += v.x*cw1.x + v.y*cw1.y + v.z*cw1.z + v.w*cw1.w;
    v = v4[2]; s += v.x*cw2.x + v.y*cw2.y + v.z*cw2.z + v.w*cw2.w;
    v = v4[3]; s += v.x*cw3.x + v.y*cw3.y + v.z*cw3.z + v.w*cw3.w;

    #pragma unroll
    for (int off = 16; off >= 1; off >>= 1)
        s = fmaxf(s, __shfl_xor_sync(0xffffffffu, s, off));
    if (lane == 0) out[b * 768 + dir * 256 + pool] = s;
}

// ---------------- launch ----------------
extern "C" void kernel_launch(void* const* d_in, const int* in_sizes, int n_in,
                              void* d_out, int out_size) {
    const float* x       = (const float*)d_in[0];
    const float* Win     = (const float*)d_in[1];
    const float* conv_w  = (const float*)d_in[2];
    const float* conv_b  = (const float*)d_in[3];
    const float* dt_bias = (const float*)d_in[4];
    const float* A_log   = (const float*)d_in[5];
    const float* Dp      = (const float*)d_in[6];
    const float* norm_w  = (const float*)d_in[7];
    const float* Wout    = (const float*)d_in[8];
    const float* gamma   = (const float*)d_in[9];
    const float* beta    = (const float*)d_in[10];
    const float* lin_w   = (const float*)d_in[11];
    const float* lin_b   = (const float*)d_in[12];
    float* out = (float*)d_out;

    k12_fused<<<NSEQ * 256, 288>>>(x, Win, dt_bias, A_log, conv_w, conv_b);
    k3_scan<<<(NSEQ * NCHUNK * 4) / 8, 256>>>();
    k4a_segscan<<<NSEQ * NH * 4, 256>>>();
    k4b_combine<<<NSEQ, 1024>>>();
    k5_fused<<<NSEQ * NCHUNK, 1024>>>(Dp, Wout, norm_w);
    k6a_bnstats<<<3 * 64, 256>>>();
    k6b_coef<<<1, 64>>>(gamma, beta, lin_w, lin_b);
    k7_pool<<<NSEQ * 256, 32>>>(out);
}